// round 8
// baseline (speedup 1.0000x reference)
#include <cuda_runtime.h>
#include <math.h>
#include <stdint.h>

#define NB 4
#define NT 4096
#define ND 1024
#define NH 64
#define SPLIT 4

// Scratch. g_Q/g_K: head-dim PAIR-PERMUTED (p(j)=2(j&3)+(j>>2) within each
// 8-block) so attention GEMM1 fragment halves (k, k+4) are 8B-adjacent.
// g_V natural [b][tok][h]; g_Vt transposed [b][h][tok] (made by transpose_v).
__device__ float g_Q[NB * NT * NH];
__device__ float g_K[NB * NT * NH];
__device__ float g_V[NB * NT * NH];
__device__ float g_Vt[NB * NH * NT];
__device__ float g_Op[SPLIT][NB * NT * NH];
__device__ float g_ml[SPLIT][NB * NT][2];
// tf32-converted, pair-permuted weights: rows 0-63 wq | 64-127 wk | 128-191 wv.
__device__ float g_Wp[192 * ND];

__device__ __forceinline__ uint32_t f2tf(float f) {
    uint32_t u;
    asm("cvt.rna.tf32.f32 %0, %1;" : "=r"(u) : "f"(f));
    return u;
}

__device__ __forceinline__ void mma8(float d[4],
                                     uint32_t a0, uint32_t a1, uint32_t a2, uint32_t a3,
                                     uint32_t b0, uint32_t b1) {
    asm volatile(
        "mma.sync.aligned.m16n8k8.row.col.f32.tf32.tf32.f32 "
        "{%0,%1,%2,%3}, {%4,%5,%6,%7}, {%8,%9}, {%0,%1,%2,%3};"
        : "+f"(d[0]), "+f"(d[1]), "+f"(d[2]), "+f"(d[3])
        : "r"(a0), "r"(a1), "r"(a2), "r"(a3), "r"(b0), "r"(b1));
}

// 8B-granule swizzle on 64-float rows: pc = pair-column (0..31).
#define SWP(r, pc) (((r) << 6) + ((((pc) ^ (((r) & 7) << 2)) << 1)))

__device__ __forceinline__ void cp16(uint32_t dst, const void* src) {
    asm volatile("cp.async.cg.shared.global [%0], [%1], 16;" :: "r"(dst), "l"(src));
}
__device__ __forceinline__ void cp_commit() { asm volatile("cp.async.commit_group;"); }
template<int N> __device__ __forceinline__ void cp_wait() {
    asm volatile("cp.async.wait_group %0;" :: "n"(N));
}

// ---------------------------------------------------------------------------
// Kernel 0: weight prepass (tf32 + pair-permute k columns for qkv's B frags).
// ---------------------------------------------------------------------------
__global__ __launch_bounds__(256) void prep_w_kernel(
    const float* __restrict__ wq,
    const float* __restrict__ wk,
    const float* __restrict__ wv)
{
    int idx = blockIdx.x * 256 + threadIdx.x;  // 192*1024
    int row = idx >> 10, k = idx & 1023;
    const float* src = (row < 64) ? wq + (size_t)row * ND
                     : (row < 128) ? wk + (size_t)(row - 64) * ND
                     : wv + (size_t)(row - 128) * ND;
    int j = k & 7;
    int p = (k & ~7) | (2 * (j & 3)) | (j >> 2);
    g_Wp[(size_t)row * ND + p] = __uint_as_float(f2tf(src[k]));
}

// ---------------------------------------------------------------------------
// Kernel 1: fused QKV projection (proven mainloop). Epilogue: Q/K with
// pair-permuted head columns (coalesced-ish row stores); V natural layout.
// ---------------------------------------------------------------------------
#define XPW 36
#define QKV_SMEM_BYTES (16896 * 4)

__device__ __forceinline__ void qkv_issue(uint32_t xbase, uint32_t wbase,
                                          const float* xsrc, int k0, int t)
{
#pragma unroll
    for (int i = 0; i < 2; i++) {
        int c = t * 2 + i;
        int row = c >> 3, j = c & 7;
        cp16(xbase + (uint32_t)(row * XPW + j * 4) * 4,
             xsrc + (size_t)row * ND + k0 + j * 4);
    }
#pragma unroll
    for (int i = 0; i < 6; i++) {
        int c = t + 256 * i;
        int row = c >> 3, j = c & 7;
        uint32_t gran = (uint32_t)((2 * j) ^ ((row & 3) << 2));
        cp16(wbase + (uint32_t)(row * 32 + gran * 2) * 4,
             g_Wp + (size_t)row * ND + k0 + j * 4);
    }
}

__global__ __launch_bounds__(256) void qkv_kernel(const float* __restrict__ x)
{
    extern __shared__ float qsm[];
    const int t = threadIdx.x;
    const int row0 = blockIdx.x * 64;
    const int w = t >> 5, lane = t & 31, g = lane >> 2, t4 = lane & 3;
    const int wr = w & 1, wc = w >> 1;

    const uint32_t smb = (uint32_t)__cvta_generic_to_shared(qsm);
    const uint32_t xoffs[2] = {smb, smb + 2304u * 4};
    const uint32_t woffs[2] = {smb + 4608u * 4, smb + 10752u * 4};
    float* const xbuf[2] = {qsm, qsm + 2304};
    float* const wbuf[2] = {qsm + 4608, qsm + 10752};

    const float* xsrc = x + (size_t)row0 * ND;

    float acc[2][6][4];
#pragma unroll
    for (int mt = 0; mt < 2; mt++)
#pragma unroll
        for (int nt = 0; nt < 6; nt++)
#pragma unroll
            for (int j = 0; j < 4; j++) acc[mt][nt][j] = 0.0f;

    qkv_issue(xoffs[0], woffs[0], xsrc, 0, t);
    cp_commit();

    for (int it = 0; it < 32; it++) {
        const int p = it & 1;
        cp_wait<0>();
        __syncthreads();
        if (it + 1 < 32) {
            qkv_issue(xoffs[p ^ 1], woffs[p ^ 1], xsrc, (it + 1) * 32, t);
            cp_commit();
        }

        const float* xb = xbuf[p];
        const float* wb = wbuf[p];
#pragma unroll
        for (int ks8 = 0; ks8 < 4; ks8++) {
            int kk = ks8 * 8;
            uint32_t a[2][4];
#pragma unroll
            for (int mt = 0; mt < 2; mt++) {
                int R = 32 * wr + 16 * mt;
                a[mt][0] = f2tf(xb[(R + g) * XPW + kk + t4]);
                a[mt][1] = f2tf(xb[(R + g + 8) * XPW + kk + t4]);
                a[mt][2] = f2tf(xb[(R + g) * XPW + kk + t4 + 4]);
                a[mt][3] = f2tf(xb[(R + g + 8) * XPW + kk + t4 + 4]);
            }
#pragma unroll
            for (int nt = 0; nt < 6; nt++) {
                int nrow = 48 * wc + 8 * nt + g;
                uint32_t gran = (uint32_t)((4 * ks8 + t4) ^ ((nrow & 3) << 2));
                float2 bv = *(const float2*)&wb[nrow * 32 + gran * 2];
                uint32_t b0 = __float_as_uint(bv.x);
                uint32_t b1 = __float_as_uint(bv.y);
                mma8(acc[0][nt], a[0][0], a[0][1], a[0][2], a[0][3], b0, b1);
                mma8(acc[1][nt], a[1][0], a[1][1], a[1][2], a[1][3], b0, b1);
            }
        }
    }

    // Epilogue: Q/K pair-permuted head cols; V natural layout (coalesced).
#pragma unroll
    for (int mt = 0; mt < 2; mt++)
#pragma unroll
        for (int nt = 0; nt < 6; nt++) {
            int gc = 48 * wc + 8 * nt + 2 * t4;
            int mm = gc >> 6;
            int h = gc & 63;
            int r1 = row0 + 32 * wr + 16 * mt + g;
            if (mm == 2) {
                g_V[(size_t)r1 * NH + h] = __uint_as_float(f2tf(acc[mt][nt][0]));
                g_V[(size_t)r1 * NH + h + 1] = __uint_as_float(f2tf(acc[mt][nt][1]));
                g_V[(size_t)(r1 + 8) * NH + h] = __uint_as_float(f2tf(acc[mt][nt][2]));
                g_V[(size_t)(r1 + 8) * NH + h + 1] = __uint_as_float(f2tf(acc[mt][nt][3]));
            } else {
                float* dst = (mm == 0) ? g_Q : g_K;
                float sc = (mm == 0) ? 0.125f : 1.0f;
                int j = gc & 7;  // = 2*t4 (even)
                int hb = h & ~7;
                int p0 = 2 * (j & 3) + (j >> 2);
                int p1 = p0 + 2;  // p(j+1) for even j
                dst[(size_t)r1 * NH + hb + p0] =
                    __uint_as_float(f2tf(acc[mt][nt][0] * sc));
                dst[(size_t)r1 * NH + hb + p1] =
                    __uint_as_float(f2tf(acc[mt][nt][1] * sc));
                dst[(size_t)(r1 + 8) * NH + hb + p0] =
                    __uint_as_float(f2tf(acc[mt][nt][2] * sc));
                dst[(size_t)(r1 + 8) * NH + hb + p1] =
                    __uint_as_float(f2tf(acc[mt][nt][3] * sc));
            }
        }
}

// ---------------------------------------------------------------------------
// Kernel 1b: V transpose, both sides coalesced via padded smem tile.
// Grid (NT/64, NB), 256 threads.
// ---------------------------------------------------------------------------
__global__ __launch_bounds__(256) void transpose_v_kernel()
{
    __shared__ float tile[64][65];
    const int b = blockIdx.y, tok0 = blockIdx.x * 64;
    const int t = threadIdx.x;
    const int r = t >> 4, c4 = (t & 15) * 4;

#pragma unroll
    for (int i = 0; i < 4; i++) {
        int tok = r + 16 * i;
        float4 v = *(const float4*)(g_V + ((size_t)(b * NT) + tok0 + tok) * NH + c4);
        tile[tok][c4 + 0] = v.x;
        tile[tok][c4 + 1] = v.y;
        tile[tok][c4 + 2] = v.z;
        tile[tok][c4 + 3] = v.w;
    }
    __syncthreads();
#pragma unroll
    for (int i = 0; i < 4; i++) {
        int h = r + 16 * i;
        float4 v = make_float4(tile[c4 + 0][h], tile[c4 + 1][h],
                               tile[c4 + 2][h], tile[c4 + 3][h]);
        *(float4*)(g_Vt + ((size_t)(b * NH) + h) * NT + tok0 + c4) = v;
    }
}

// ---------------------------------------------------------------------------
// Kernel 2: flash attention. BLOCK_M=128, BLOCK_N=64, **8 warps, 16 rows
// each** (latency-hiding experiment: per-warp serial chain halved, warps/SM
// doubled). LDS.64 fragment reads under SWP. split-KV=4.
// Dynamic smem: Q 32KB | K 2x16KB | V 16KB = 80KB.
// ---------------------------------------------------------------------------
#define ATTN_SMEM_BYTES (20480 * 4)

__global__ __launch_bounds__(256) void attn_kernel()
{
    extern __shared__ float smem[];
    float* qs  = smem;                   // 128x64 (permuted head cols)
    float* ks0 = smem + 8192;            // 64x64 (buffer 0)
    float* ks1 = smem + 12288;           // 64x64 (buffer 1)
    float* vs  = smem + 16384;           // 64 h-rows x 64 key-cols

    const int b = blockIdx.y, q0 = blockIdx.x * 128, sp = blockIdx.z;
    const int t = threadIdx.x, w = t >> 5, lane = t & 31;
    const int g = lane >> 2, t4 = lane & 3;
    const int r0 = w * 16;  // warp owns rows [r0, r0+16)

    const int sp_off = sp * (NT / SPLIT);
    const float* Qp  = g_Q + ((size_t)b * NT + q0) * NH;
    const float* Kp  = g_K + (size_t)(b * NT + sp_off) * NH;
    const float* Vtp = g_Vt + (size_t)b * NH * NT + sp_off;

    const uint32_t smb = (uint32_t)__cvta_generic_to_shared(smem);
    const uint32_t qsb = smb;
    const uint32_t ksb = smb + 8192 * 4;
    const uint32_t vsb = smb + 16384 * 4;

    // Loaders (256 threads): rows (t>>4)+16i, col group (t&15)*4.
    const int lr = t >> 4, lc = (t & 15) * 4;
    const int lp = lc >> 1;  // even pair index -> 16B-aligned under SWP

    // Prologue: group A = Q(128 rows) + K(0); group B = V(0) transposed.
#pragma unroll
    for (int i = 0; i < 8; i++)
        cp16(qsb + (uint32_t)SWP(lr + 16 * i, lp) * 4,
             Qp + (size_t)(lr + 16 * i) * NH + lc);
#pragma unroll
    for (int i = 0; i < 4; i++)
        cp16(ksb + (uint32_t)SWP(lr + 16 * i, lp) * 4,
             Kp + (size_t)(lr + 16 * i) * NH + lc);
    cp_commit();
#pragma unroll
    for (int i = 0; i < 4; i++)
        cp16(vsb + (uint32_t)SWP(lr + 16 * i, lp) * 4,
             Vtp + (size_t)(lr + 16 * i) * NT + lc);
    cp_commit();

    float o[8][4];
    float m[2] = {-1e30f, -1e30f}, l[2] = {0.0f, 0.0f};
#pragma unroll
    for (int nt = 0; nt < 8; nt++)
#pragma unroll
        for (int j = 0; j < 4; j++) o[nt][j] = 0.0f;

    const int NIT = (NT / SPLIT) / 64;  // 16

    for (int it = 0; it < NIT; it++) {
        const float* ksp = (it & 1) ? ks1 : ks0;
        const uint32_t knb = (it & 1) ? ksb : (ksb + 4096 * 4);
        cp_wait<1>();
        __syncthreads();
        if (it + 1 < NIT) {
#pragma unroll
            for (int i = 0; i < 4; i++)
                cp16(knb + (uint32_t)SWP(lr + 16 * i, lp) * 4,
                     Kp + (size_t)((it + 1) * 64 + lr + 16 * i) * NH + lc);
        }
        cp_commit();

        // GEMM1: S = Q @ K^T (all fragments LDS.64).
        float s[8][4];
#pragma unroll
        for (int nt = 0; nt < 8; nt++)
            s[nt][0] = s[nt][1] = s[nt][2] = s[nt][3] = 0.0f;
#pragma unroll
        for (int kk8 = 0; kk8 < 8; kk8++) {
            int kp = kk8 * 4 + t4;  // pair index: (logical k, k+4)
            float2 p0 = *(const float2*)&qs[SWP(r0 + g, kp)];
            float2 p1 = *(const float2*)&qs[SWP(r0 + g + 8, kp)];
            uint32_t a0 = __float_as_uint(p0.x);
            uint32_t a1 = __float_as_uint(p1.x);
            uint32_t a2 = __float_as_uint(p0.y);
            uint32_t a3 = __float_as_uint(p1.y);
#pragma unroll
            for (int nt = 0; nt < 8; nt++) {
                float2 bv = *(const float2*)&ksp[SWP(nt * 8 + g, kp)];
                mma8(s[nt], a0, a1, a2, a3,
                     __float_as_uint(bv.x), __float_as_uint(bv.y));
            }
        }

        // Online softmax (row stats across quad via shfl).
        float mx0 = -1e30f, mx1 = -1e30f;
#pragma unroll
        for (int nt = 0; nt < 8; nt++) {
            mx0 = fmaxf(mx0, fmaxf(s[nt][0], s[nt][1]));
            mx1 = fmaxf(mx1, fmaxf(s[nt][2], s[nt][3]));
        }
        mx0 = fmaxf(mx0, __shfl_xor_sync(0xffffffffu, mx0, 1));
        mx0 = fmaxf(mx0, __shfl_xor_sync(0xffffffffu, mx0, 2));
        mx1 = fmaxf(mx1, __shfl_xor_sync(0xffffffffu, mx1, 1));
        mx1 = fmaxf(mx1, __shfl_xor_sync(0xffffffffu, mx1, 2));
        float mn0 = fmaxf(m[0], mx0), mn1 = fmaxf(m[1], mx1);
        float c0 = __expf(m[0] - mn0), c1 = __expf(m[1] - mn1);
        float sum0 = 0.0f, sum1 = 0.0f;
#pragma unroll
        for (int nt = 0; nt < 8; nt++) {
            s[nt][0] = __expf(s[nt][0] - mn0);
            s[nt][1] = __expf(s[nt][1] - mn0);
            s[nt][2] = __expf(s[nt][2] - mn1);
            s[nt][3] = __expf(s[nt][3] - mn1);
            sum0 += s[nt][0] + s[nt][1];
            sum1 += s[nt][2] + s[nt][3];
            o[nt][0] *= c0; o[nt][1] *= c0;
            o[nt][2] *= c1; o[nt][3] *= c1;
        }
        sum0 += __shfl_xor_sync(0xffffffffu, sum0, 1);
        sum0 += __shfl_xor_sync(0xffffffffu, sum0, 2);
        sum1 += __shfl_xor_sync(0xffffffffu, sum1, 1);
        sum1 += __shfl_xor_sync(0xffffffffu, sum1, 2);
        l[0] = l[0] * c0 + sum0;
        l[1] = l[1] * c1 + sum1;
        m[0] = mn0;
        m[1] = mn1;

        cp_wait<1>();
        __syncthreads();

        // GEMM2: O += P @ V. A = S C-frag (permuted-k); B via LDS.64 from
        // transposed V tile (keys kb*8+2t4, +1 adjacent).
#pragma unroll
        for (int kb = 0; kb < 8; kb++) {
            uint32_t a0 = f2tf(s[kb][0]);
            uint32_t a1 = f2tf(s[kb][2]);
            uint32_t a2 = f2tf(s[kb][1]);
            uint32_t a3 = f2tf(s[kb][3]);
#pragma unroll
            for (int nt = 0; nt < 8; nt++) {
                float2 bv = *(const float2*)&vs[SWP(nt * 8 + g, kb * 4 + t4)];
                mma8(o[nt], a0, a1, a2, a3,
                     __float_as_uint(bv.x), __float_as_uint(bv.y));
            }
        }
        __syncthreads();

        if (it + 1 < NIT) {
#pragma unroll
            for (int i = 0; i < 4; i++)
                cp16(vsb + (uint32_t)SWP(lr + 16 * i, lp) * 4,
                     Vtp + (size_t)(lr + 16 * i) * NT + (it + 1) * 64 + lc);
        }
        cp_commit();
    }

    // Epilogue: unnormalized numerator + (m, l) per split.
    float* Op = g_Op[sp] + ((size_t)b * NT + q0) * NH;
#pragma unroll
    for (int nt = 0; nt < 8; nt++) {
        int c = nt * 8 + 2 * t4;
        *(float2*)&Op[(size_t)(r0 + g) * NH + c] = make_float2(o[nt][0], o[nt][1]);
        *(float2*)&Op[(size_t)(r0 + g + 8) * NH + c] = make_float2(o[nt][2], o[nt][3]);
    }
    if (t4 == 0) {
        int rr = b * NT + q0;
        g_ml[sp][rr + r0 + g][0] = m[0];
        g_ml[sp][rr + r0 + g][1] = l[0];
        g_ml[sp][rr + r0 + g + 8][0] = m[1];
        g_ml[sp][rr + r0 + g + 8][1] = l[1];
    }
}

// ---------------------------------------------------------------------------
// Kernel 3: merge the SPLIT KV-splits.
// ---------------------------------------------------------------------------
__global__ __launch_bounds__(256) void combine_kernel(float* __restrict__ out)
{
    int row = blockIdx.x * 4 + (threadIdx.x >> 6);
    int c = threadIdx.x & 63;
    float M = -1e30f;
#pragma unroll
    for (int sp = 0; sp < SPLIT; sp++) M = fmaxf(M, g_ml[sp][row][0]);
    float L = 0.0f, acc = 0.0f;
    size_t idx = (size_t)row * NH + c;
#pragma unroll
    for (int sp = 0; sp < SPLIT; sp++) {
        float e = __expf(g_ml[sp][row][0] - M);
        L += e * g_ml[sp][row][1];
        acc += e * g_Op[sp][idx];
    }
    out[idx] = acc / L;
}

// ---------------------------------------------------------------------------
extern "C" void kernel_launch(void* const* d_in, const int* in_sizes, int n_in,
                              void* d_out, int out_size)
{
    const float* x  = (const float*)d_in[0];
    const float* wq = (const float*)d_in[1];
    const float* wk = (const float*)d_in[2];
    const float* wv = (const float*)d_in[3];
    float* out = (float*)d_out;
    (void)in_sizes; (void)n_in; (void)out_size;

    cudaFuncSetAttribute((const void*)qkv_kernel,
                         cudaFuncAttributeMaxDynamicSharedMemorySize,
                         QKV_SMEM_BYTES);
    cudaFuncSetAttribute((const void*)attn_kernel,
                         cudaFuncAttributeMaxDynamicSharedMemorySize,
                         ATTN_SMEM_BYTES);
    cudaFuncSetAttribute((const void*)attn_kernel,
                         cudaFuncAttributePreferredSharedMemoryCarveout,
                         cudaSharedmemCarveoutMaxShared);

    prep_w_kernel<<<(192 * ND) / 256, 256>>>(wq, wk, wv);
    qkv_kernel<<<(NB * NT) / 64, 256, QKV_SMEM_BYTES>>>(x);
    transpose_v_kernel<<<dim3(NT / 64, NB), 256>>>();
    attn_kernel<<<dim3(NT / 128, NB, SPLIT), 256, ATTN_SMEM_BYTES>>>();
    combine_kernel<<<(NB * NT) / 4, 256>>>(out);
}

// round 13
// speedup vs baseline: 1.9164x; 1.9164x over previous
#include <cuda_runtime.h>
#include <cuda_fp16.h>
#include <math.h>
#include <stdint.h>

#define NB 4
#define NT 4096
#define ND 1024
#define NH 64
#define SPLIT 4

// Scratch: fp16 Q (pre-scaled by 1/8), K, V natural [b][tok][h]; V^T [b][h][tok].
__device__ __half g_Q[NB * NT * NH];
__device__ __half g_K[NB * NT * NH];
__device__ __half g_V[NB * NT * NH];
__device__ __half g_Vt[NB * NH * NT];
__device__ float g_Op[SPLIT][NB * NT * NH];
__device__ float g_ml[SPLIT][NB * NT][2];
// tf32-converted, pair-permuted weights for qkv: 0-63 wq | 64-127 wk | 128-191 wv.
__device__ float g_Wp[192 * ND];

__device__ __forceinline__ uint32_t f2tf(float f) {
    uint32_t u;
    asm("cvt.rna.tf32.f32 %0, %1;" : "=r"(u) : "f"(f));
    return u;
}

// tf32 m16n8k8 (qkv kernel).
__device__ __forceinline__ void mma8(float d[4],
                                     uint32_t a0, uint32_t a1, uint32_t a2, uint32_t a3,
                                     uint32_t b0, uint32_t b1) {
    asm volatile(
        "mma.sync.aligned.m16n8k8.row.col.f32.tf32.tf32.f32 "
        "{%0,%1,%2,%3}, {%4,%5,%6,%7}, {%8,%9}, {%0,%1,%2,%3};"
        : "+f"(d[0]), "+f"(d[1]), "+f"(d[2]), "+f"(d[3])
        : "r"(a0), "r"(a1), "r"(a2), "r"(a3), "r"(b0), "r"(b1));
}

// fp16 m16n8k16 with fp32 accumulate (attention).
__device__ __forceinline__ void hmma(float d[4],
                                     uint32_t a0, uint32_t a1, uint32_t a2, uint32_t a3,
                                     uint32_t b0, uint32_t b1) {
    asm volatile(
        "mma.sync.aligned.m16n8k16.row.col.f32.f16.f16.f32 "
        "{%0,%1,%2,%3}, {%4,%5,%6,%7}, {%8,%9}, {%0,%1,%2,%3};"
        : "+f"(d[0]), "+f"(d[1]), "+f"(d[2]), "+f"(d[3])
        : "r"(a0), "r"(a1), "r"(a2), "r"(a3), "r"(b0), "r"(b1));
}

__device__ __forceinline__ uint32_t f22h2(float lo, float hi) {
    __half2 h = __floats2half2_rn(lo, hi);  // .x = lo (low 16 bits)
    return *reinterpret_cast<uint32_t*>(&h);
}

// fp16 tile swizzles: rows of 64 halves (128 B). 16B-chunk swizzle for
// cp.async, 4B-granule swizzle (consistent) for half2 fragment loads.
#define SWC(r, c16) (((r) << 7) + ((((c16) ^ ((r) & 7))) << 4))
#define SWH2(r, hp) (((r) << 7) + ((((hp) ^ (((r) & 7) << 2))) << 2))

__device__ __forceinline__ void cp16(uint32_t dst, const void* src) {
    asm volatile("cp.async.cg.shared.global [%0], [%1], 16;" :: "r"(dst), "l"(src));
}
__device__ __forceinline__ void cp_commit() { asm volatile("cp.async.commit_group;"); }
template<int N> __device__ __forceinline__ void cp_wait() {
    asm volatile("cp.async.wait_group %0;" :: "n"(N));
}

// ---------------------------------------------------------------------------
// Kernel 0: weight prepass (tf32 + pair-permute k columns for qkv's B frags).
// ---------------------------------------------------------------------------
__global__ __launch_bounds__(256) void prep_w_kernel(
    const float* __restrict__ wq,
    const float* __restrict__ wk,
    const float* __restrict__ wv)
{
    int idx = blockIdx.x * 256 + threadIdx.x;  // 192*1024
    int row = idx >> 10, k = idx & 1023;
    const float* src = (row < 64) ? wq + (size_t)row * ND
                     : (row < 128) ? wk + (size_t)(row - 64) * ND
                     : wv + (size_t)(row - 128) * ND;
    int j = k & 7;
    int p = (k & ~7) | (2 * (j & 3)) | (j >> 2);
    g_Wp[(size_t)row * ND + p] = __uint_as_float(f2tf(src[k]));
}

// ---------------------------------------------------------------------------
// Kernel 1: fused QKV projection (proven tf32 mainloop). Epilogue now emits
// __half Q (scaled by 1/8), K, V in natural layout.
// ---------------------------------------------------------------------------
#define XPW 36
#define QKV_SMEM_BYTES (16896 * 4)

__device__ __forceinline__ void qkv_issue(uint32_t xbase, uint32_t wbase,
                                          const float* xsrc, int k0, int t)
{
#pragma unroll
    for (int i = 0; i < 2; i++) {
        int c = t * 2 + i;
        int row = c >> 3, j = c & 7;
        cp16(xbase + (uint32_t)(row * XPW + j * 4) * 4,
             xsrc + (size_t)row * ND + k0 + j * 4);
    }
#pragma unroll
    for (int i = 0; i < 6; i++) {
        int c = t + 256 * i;
        int row = c >> 3, j = c & 7;
        uint32_t gran = (uint32_t)((2 * j) ^ ((row & 3) << 2));
        cp16(wbase + (uint32_t)(row * 32 + gran * 2) * 4,
             g_Wp + (size_t)row * ND + j * 4 + k0);
    }
}

__global__ __launch_bounds__(256) void qkv_kernel(const float* __restrict__ x)
{
    extern __shared__ float qsm[];
    const int t = threadIdx.x;
    const int row0 = blockIdx.x * 64;
    const int w = t >> 5, lane = t & 31, g = lane >> 2, t4 = lane & 3;
    const int wr = w & 1, wc = w >> 1;

    const uint32_t smb = (uint32_t)__cvta_generic_to_shared(qsm);
    const uint32_t xoffs[2] = {smb, smb + 2304u * 4};
    const uint32_t woffs[2] = {smb + 4608u * 4, smb + 10752u * 4};
    float* const xbuf[2] = {qsm, qsm + 2304};
    float* const wbuf[2] = {qsm + 4608, qsm + 10752};

    const float* xsrc = x + (size_t)row0 * ND;

    float acc[2][6][4];
#pragma unroll
    for (int mt = 0; mt < 2; mt++)
#pragma unroll
        for (int nt = 0; nt < 6; nt++)
#pragma unroll
            for (int j = 0; j < 4; j++) acc[mt][nt][j] = 0.0f;

    qkv_issue(xoffs[0], woffs[0], xsrc, 0, t);
    cp_commit();

    for (int it = 0; it < 32; it++) {
        const int p = it & 1;
        cp_wait<0>();
        __syncthreads();
        if (it + 1 < 32) {
            qkv_issue(xoffs[p ^ 1], woffs[p ^ 1], xsrc, (it + 1) * 32, t);
            cp_commit();
        }

        const float* xb = xbuf[p];
        const float* wb = wbuf[p];
#pragma unroll
        for (int ks8 = 0; ks8 < 4; ks8++) {
            int kk = ks8 * 8;
            uint32_t a[2][4];
#pragma unroll
            for (int mt = 0; mt < 2; mt++) {
                int R = 32 * wr + 16 * mt;
                a[mt][0] = f2tf(xb[(R + g) * XPW + kk + t4]);
                a[mt][1] = f2tf(xb[(R + g + 8) * XPW + kk + t4]);
                a[mt][2] = f2tf(xb[(R + g) * XPW + kk + t4 + 4]);
                a[mt][3] = f2tf(xb[(R + g + 8) * XPW + kk + t4 + 4]);
            }
#pragma unroll
            for (int nt = 0; nt < 6; nt++) {
                int nrow = 48 * wc + 8 * nt + g;
                uint32_t gran = (uint32_t)((4 * ks8 + t4) ^ ((nrow & 3) << 2));
                float2 bv = *(const float2*)&wb[nrow * 32 + gran * 2];
                uint32_t b0 = __float_as_uint(bv.x);
                uint32_t b1 = __float_as_uint(bv.y);
                mma8(acc[0][nt], a[0][0], a[0][1], a[0][2], a[0][3], b0, b1);
                mma8(acc[1][nt], a[1][0], a[1][1], a[1][2], a[1][3], b0, b1);
            }
        }
    }

    // Epilogue: route to Q/K/V as __half, natural layout.
#pragma unroll
    for (int mt = 0; mt < 2; mt++)
#pragma unroll
        for (int nt = 0; nt < 6; nt++) {
            int gc = 48 * wc + 8 * nt + 2 * t4;
            int mm = gc >> 6;
            int h = gc & 63;
            __half* dst = (mm == 0) ? g_Q : (mm == 1) ? g_K : g_V;
            float sc = (mm == 0) ? 0.125f : 1.0f;
            int r1 = row0 + 32 * wr + 16 * mt + g;
            dst[(size_t)r1 * NH + h]           = __float2half_rn(acc[mt][nt][0] * sc);
            dst[(size_t)r1 * NH + h + 1]       = __float2half_rn(acc[mt][nt][1] * sc);
            dst[(size_t)(r1 + 8) * NH + h]     = __float2half_rn(acc[mt][nt][2] * sc);
            dst[(size_t)(r1 + 8) * NH + h + 1] = __float2half_rn(acc[mt][nt][3] * sc);
        }
}

// ---------------------------------------------------------------------------
// Kernel 1b: V transpose (half), both sides coalesced. Grid (NT/64, NB).
// ---------------------------------------------------------------------------
__global__ __launch_bounds__(256) void transpose_v_kernel()
{
    __shared__ __half tile[64][72];  // 72-half pitch = 144B (16B-aligned)
    const int b = blockIdx.y, tok0 = blockIdx.x * 64;
    const int t = threadIdx.x;

    // Load: 64 rows x 64 halves; thread: row t>>2, halves (t&3)*16 .. +15.
    {
        int row = t >> 2, c = (t & 3) * 16;
        const uint4* src = (const uint4*)(g_V + ((size_t)(b * NT) + tok0 + row) * NH + c);
        *(uint4*)&tile[row][c]     = src[0];
        *(uint4*)&tile[row][c + 8] = src[1];
    }
    __syncthreads();
    // Store transposed: thread handles h = (t>>5)+8i, toks (t&31)*2, +1.
#pragma unroll
    for (int i = 0; i < 8; i++) {
        int h = (t >> 5) + 8 * i;
        int tk = (t & 31) * 2;
        uint32_t v = f22h2(__half2float(tile[tk][h]), __half2float(tile[tk + 1][h]));
        *(uint32_t*)(g_Vt + ((size_t)(b * NH) + h) * NT + tok0 + tk) = v;
    }
}

// ---------------------------------------------------------------------------
// Kernel 2: flash attention, fp16 mma (m16n8k16, fp32 accum). BLOCK_M=128,
// BLOCK_N=64, 4 warps (2 m-tiles, B-frags shared), split-KV=4.
// fp16 fragment layouts are natural: GEMM1 A/B half-pairs = adjacent head
// cols; GEMM2 A = S C-frag directly (no permutation); GEMM2 B = adjacent
// key-pairs from transposed V. Smem: Q 16K | K 2x8K | V^T 8K = 40KB.
// ---------------------------------------------------------------------------
#define AT_SMEM_BYTES 40960
#define AT_QS 0
#define AT_K0 16384
#define AT_K1 24576
#define AT_VS 32768

__global__ __launch_bounds__(128) void attn_kernel()
{
    extern __shared__ __half hsm[];
    const char* smc = (const char*)hsm;
    const uint32_t smb = (uint32_t)__cvta_generic_to_shared(hsm);

    const int b = blockIdx.y, q0 = blockIdx.x * 128, sp = blockIdx.z;
    const int t = threadIdx.x, w = t >> 5, lane = t & 31;
    const int g = lane >> 2, t4 = lane & 3;
    const int r0 = w * 32;

    const int sp_off = sp * (NT / SPLIT);
    const __half* Qp  = g_Q + ((size_t)b * NT + q0) * NH;
    const __half* Kp  = g_K + ((size_t)(b * NT) + sp_off) * NH;
    const __half* Vtp = g_Vt + (size_t)b * NH * NT + sp_off;

    // Loaders: lr = t>>3 (0..15), lc16 = t&7 (16B chunk = 8 halves).
    const int lr = t >> 3, lc16 = t & 7;

    // Prologue: group A = Q(128 rows) + K(0); group B = V^T(0).
#pragma unroll
    for (int i = 0; i < 8; i++) {
        int row = lr + 16 * i;
        cp16(smb + AT_QS + (uint32_t)SWC(row, lc16),
             Qp + (size_t)row * NH + lc16 * 8);
    }
#pragma unroll
    for (int i = 0; i < 4; i++) {
        int row = lr + 16 * i;
        cp16(smb + AT_K0 + (uint32_t)SWC(row, lc16),
             Kp + (size_t)row * NH + lc16 * 8);
    }
    cp_commit();
#pragma unroll
    for (int i = 0; i < 4; i++) {
        int row = lr + 16 * i;
        cp16(smb + AT_VS + (uint32_t)SWC(row, lc16),
             Vtp + (size_t)row * NT + lc16 * 8);
    }
    cp_commit();

    float o[2][8][4];
    float m[2][2], l[2][2];
#pragma unroll
    for (int mt = 0; mt < 2; mt++) {
        m[mt][0] = m[mt][1] = -1e30f;
        l[mt][0] = l[mt][1] = 0.0f;
#pragma unroll
        for (int nt = 0; nt < 8; nt++)
#pragma unroll
            for (int j = 0; j < 4; j++) o[mt][nt][j] = 0.0f;
    }

    const int NIT = (NT / SPLIT) / 64;  // 16

    for (int it = 0; it < NIT; it++) {
        const uint32_t kcur = (it & 1) ? AT_K1 : AT_K0;
        const uint32_t knxt = (it & 1) ? AT_K0 : AT_K1;
        cp_wait<1>();
        __syncthreads();
        if (it + 1 < NIT) {
#pragma unroll
            for (int i = 0; i < 4; i++) {
                int row = lr + 16 * i;
                cp16(smb + knxt + (uint32_t)SWC(row, lc16),
                     Kp + (size_t)((it + 1) * 64 + row) * NH + lc16 * 8);
            }
        }
        cp_commit();

        // GEMM1: S = Q @ K^T (fp16, fp32 accum).
        float s[2][8][4];
#pragma unroll
        for (int mt = 0; mt < 2; mt++)
#pragma unroll
            for (int nt = 0; nt < 8; nt++)
                s[mt][nt][0] = s[mt][nt][1] = s[mt][nt][2] = s[mt][nt][3] = 0.0f;
#pragma unroll
        for (int kk = 0; kk < 4; kk++) {
            int hp0 = kk * 8 + t4, hp1 = hp0 + 4;
            uint32_t a[2][4];
#pragma unroll
            for (int mt = 0; mt < 2; mt++) {
                int ar = r0 + 16 * mt;
                a[mt][0] = *(const uint32_t*)(smc + AT_QS + SWH2(ar + g, hp0));
                a[mt][1] = *(const uint32_t*)(smc + AT_QS + SWH2(ar + g + 8, hp0));
                a[mt][2] = *(const uint32_t*)(smc + AT_QS + SWH2(ar + g, hp1));
                a[mt][3] = *(const uint32_t*)(smc + AT_QS + SWH2(ar + g + 8, hp1));
            }
#pragma unroll
            for (int nt = 0; nt < 8; nt++) {
                int kr = nt * 8 + g;
                uint32_t b0 = *(const uint32_t*)(smc + kcur + SWH2(kr, hp0));
                uint32_t b1 = *(const uint32_t*)(smc + kcur + SWH2(kr, hp1));
                hmma(s[0][nt], a[0][0], a[0][1], a[0][2], a[0][3], b0, b1);
                hmma(s[1][nt], a[1][0], a[1][1], a[1][2], a[1][3], b0, b1);
            }
        }

        // Online softmax per m-tile (fp32).
#pragma unroll
        for (int mt = 0; mt < 2; mt++) {
            float mx0 = -1e30f, mx1 = -1e30f;
#pragma unroll
            for (int nt = 0; nt < 8; nt++) {
                mx0 = fmaxf(mx0, fmaxf(s[mt][nt][0], s[mt][nt][1]));
                mx1 = fmaxf(mx1, fmaxf(s[mt][nt][2], s[mt][nt][3]));
            }
            mx0 = fmaxf(mx0, __shfl_xor_sync(0xffffffffu, mx0, 1));
            mx0 = fmaxf(mx0, __shfl_xor_sync(0xffffffffu, mx0, 2));
            mx1 = fmaxf(mx1, __shfl_xor_sync(0xffffffffu, mx1, 1));
            mx1 = fmaxf(mx1, __shfl_xor_sync(0xffffffffu, mx1, 2));
            float mn0 = fmaxf(m[mt][0], mx0), mn1 = fmaxf(m[mt][1], mx1);
            float c0 = __expf(m[mt][0] - mn0), c1 = __expf(m[mt][1] - mn1);
            float sum0 = 0.0f, sum1 = 0.0f;
#pragma unroll
            for (int nt = 0; nt < 8; nt++) {
                s[mt][nt][0] = __expf(s[mt][nt][0] - mn0);
                s[mt][nt][1] = __expf(s[mt][nt][1] - mn0);
                s[mt][nt][2] = __expf(s[mt][nt][2] - mn1);
                s[mt][nt][3] = __expf(s[mt][nt][3] - mn1);
                sum0 += s[mt][nt][0] + s[mt][nt][1];
                sum1 += s[mt][nt][2] + s[mt][nt][3];
                o[mt][nt][0] *= c0; o[mt][nt][1] *= c0;
                o[mt][nt][2] *= c1; o[mt][nt][3] *= c1;
            }
            sum0 += __shfl_xor_sync(0xffffffffu, sum0, 1);
            sum0 += __shfl_xor_sync(0xffffffffu, sum0, 2);
            sum1 += __shfl_xor_sync(0xffffffffu, sum1, 1);
            sum1 += __shfl_xor_sync(0xffffffffu, sum1, 2);
            l[mt][0] = l[mt][0] * c0 + sum0;
            l[mt][1] = l[mt][1] * c1 + sum1;
            m[mt][0] = mn0;
            m[mt][1] = mn1;
        }

        cp_wait<1>();
        __syncthreads();

        // GEMM2: O += P @ V. A = S C-frag packed to half2 (natural mapping);
        // B = adjacent key-pairs from V^T tile.
#pragma unroll
        for (int kb = 0; kb < 4; kb++) {
            int hp0 = kb * 8 + t4, hp1 = hp0 + 4;
            uint32_t a[2][4];
#pragma unroll
            for (int mt = 0; mt < 2; mt++) {
                a[mt][0] = f22h2(s[mt][2 * kb][0], s[mt][2 * kb][1]);
                a[mt][1] = f22h2(s[mt][2 * kb][2], s[mt][2 * kb][3]);
                a[mt][2] = f22h2(s[mt][2 * kb + 1][0], s[mt][2 * kb + 1][1]);
                a[mt][3] = f22h2(s[mt][2 * kb + 1][2], s[mt][2 * kb + 1][3]);
            }
#pragma unroll
            for (int nt = 0; nt < 8; nt++) {
                int vr = nt * 8 + g;
                uint32_t b0 = *(const uint32_t*)(smc + AT_VS + SWH2(vr, hp0));
                uint32_t b1 = *(const uint32_t*)(smc + AT_VS + SWH2(vr, hp1));
                hmma(o[0][nt], a[0][0], a[0][1], a[0][2], a[0][3], b0, b1);
                hmma(o[1][nt], a[1][0], a[1][1], a[1][2], a[1][3], b0, b1);
            }
        }
        __syncthreads();

        if (it + 1 < NIT) {
#pragma unroll
            for (int i = 0; i < 4; i++) {
                int row = lr + 16 * i;
                cp16(smb + AT_VS + (uint32_t)SWC(row, lc16),
                     Vtp + (size_t)row * NT + (it + 1) * 64 + lc16 * 8);
            }
        }
        cp_commit();
    }

    // Epilogue: unnormalized numerator + (m, l) per split (fp32).
    float* Op = g_Op[sp] + ((size_t)b * NT + q0) * NH;
#pragma unroll
    for (int mt = 0; mt < 2; mt++) {
        int ar = r0 + 16 * mt;
#pragma unroll
        for (int nt = 0; nt < 8; nt++) {
            int c = nt * 8 + 2 * t4;
            *(float2*)&Op[(size_t)(ar + g) * NH + c] =
                make_float2(o[mt][nt][0], o[mt][nt][1]);
            *(float2*)&Op[(size_t)(ar + g + 8) * NH + c] =
                make_float2(o[mt][nt][2], o[mt][nt][3]);
        }
        if (t4 == 0) {
            int rr = b * NT + q0;
            g_ml[sp][rr + ar + g][0] = m[mt][0];
            g_ml[sp][rr + ar + g][1] = l[mt][0];
            g_ml[sp][rr + ar + g + 8][0] = m[mt][1];
            g_ml[sp][rr + ar + g + 8][1] = l[mt][1];
        }
    }
}

// ---------------------------------------------------------------------------
// Kernel 3: merge the SPLIT KV-splits.
// ---------------------------------------------------------------------------
__global__ __launch_bounds__(256) void combine_kernel(float* __restrict__ out)
{
    int row = blockIdx.x * 4 + (threadIdx.x >> 6);
    int c = threadIdx.x & 63;
    float M = -1e30f;
#pragma unroll
    for (int sp = 0; sp < SPLIT; sp++) M = fmaxf(M, g_ml[sp][row][0]);
    float L = 0.0f, acc = 0.0f;
    size_t idx = (size_t)row * NH + c;
#pragma unroll
    for (int sp = 0; sp < SPLIT; sp++) {
        float e = __expf(g_ml[sp][row][0] - M);
        L += e * g_ml[sp][row][1];
        acc += e * g_Op[sp][idx];
    }
    out[idx] = acc / L;
}

// ---------------------------------------------------------------------------
extern "C" void kernel_launch(void* const* d_in, const int* in_sizes, int n_in,
                              void* d_out, int out_size)
{
    const float* x  = (const float*)d_in[0];
    const float* wq = (const float*)d_in[1];
    const float* wk = (const float*)d_in[2];
    const float* wv = (const float*)d_in[3];
    float* out = (float*)d_out;
    (void)in_sizes; (void)n_in; (void)out_size;

    cudaFuncSetAttribute((const void*)qkv_kernel,
                         cudaFuncAttributeMaxDynamicSharedMemorySize,
                         QKV_SMEM_BYTES);
    cudaFuncSetAttribute((const void*)attn_kernel,
                         cudaFuncAttributeMaxDynamicSharedMemorySize,
                         AT_SMEM_BYTES);

    prep_w_kernel<<<(192 * ND) / 256, 256>>>(wq, wk, wv);
    qkv_kernel<<<(NB * NT) / 64, 256, QKV_SMEM_BYTES>>>(x);
    transpose_v_kernel<<<dim3(NT / 64, NB), 256>>>();
    attn_kernel<<<dim3(NT / 128, NB, SPLIT), 128, AT_SMEM_BYTES>>>();
    combine_kernel<<<(NB * NT) / 4, 256>>>(out);
}